// round 6
// baseline (speedup 1.0000x reference)
#include <cuda_runtime.h>

// Problem constants (fixed by the reference)
#define T_TOTAL   262144
#define S_DIM     512
#define K_ROWS    258       // NUM_KNOTS + DEGREE - 1
#define NKNOTS    262       // NUM_KNOTS + 2*DEGREE
#define DEG       3

// Scratch for weight row sums (allocation-free per harness rules)
__device__ float g_rowsum[K_ROWS];

// ---------------------------------------------------------------------------
// Kernel 1: rowsum[r] = sum_s W[r, s]   (258 x 512, negligible cost)
// ---------------------------------------------------------------------------
__global__ void rowsum_kernel(const float* __restrict__ weights) {
    const int row = blockIdx.x;
    float s = 0.0f;
    for (int c = threadIdx.x; c < S_DIM; c += blockDim.x)
        s += weights[row * S_DIM + c];
    // warp reduce
    #pragma unroll
    for (int o = 16; o > 0; o >>= 1)
        s += __shfl_down_sync(0xffffffffu, s, o);
    __shared__ float ws[4];
    const int w = threadIdx.x >> 5;
    if ((threadIdx.x & 31) == 0) ws[w] = s;
    __syncthreads();
    if (threadIdx.x == 0)
        g_rowsum[row] = ws[0] + ws[1] + ws[2] + ws[3];
}

// ---------------------------------------------------------------------------
// Kernel 2: per time t — find span, local de Boor (4 coeffs), then
//           out[t, :] = c0*W[b] + c1*W[b+1] + c2*W[b+2] + c3*W[b+3]
//           sum[t]    = c . rowsum[b..b+3]
// 512 threads/block, 4 times/block, 128 threads/time, 1 float4/thread.
// ---------------------------------------------------------------------------
__global__ __launch_bounds__(512)
void bspline_kernel(const float* __restrict__ times,
                    const float* __restrict__ weights,
                    const float* __restrict__ knots,
                    float* __restrict__ out)
{
    __shared__ float s_c[4][4];
    __shared__ int   s_base[4];

    const int tl   = threadIdx.x >> 7;   // 0..3: which time in this block
    const int lane = threadIdx.x & 127;  // 0..127: column group
    const int tIdx = (blockIdx.x << 2) + tl;

    if (lane == 0) {
        const float t = times[tIdx];
        float c0 = 0.f, c1 = 0.f, c2 = 0.f, c3 = 0.f, sum = 0.f;
        int base = 0;

        // Valid half-open span exists only if t < knots[258] (= t_max).
        // t == t_max => reference basis row is all zeros (half-open intervals).
        if (t < __ldg(&knots[NKNOTS - DEG - 1])) {
            // binary search: largest i in [3, 257] with knots[i] <= t
            int lo = DEG, hi = NKNOTS - DEG - 2;   // 3 .. 257
            while (lo < hi) {
                const int mid = (lo + hi + 1) >> 1;
                if (__ldg(&knots[mid]) <= t) lo = mid; else hi = mid - 1;
            }
            const int i = lo;  // knots[i] <= t < knots[i+1], span non-empty

            // Local de Boor triangle (Piegl & Tiller A2.2): all denominators
            // span the non-empty interval [knots[i], knots[i+1]] => > 0.
            float Nv[DEG + 1];
            float left[DEG + 1], right[DEG + 1];
            Nv[0] = 1.0f;
            #pragma unroll
            for (int j = 1; j <= DEG; j++) {
                left[j]  = t - __ldg(&knots[i + 1 - j]);
                right[j] = __ldg(&knots[i + j]) - t;
                float saved = 0.0f;
                #pragma unroll
                for (int r = 0; r < j; r++) {
                    const float temp = Nv[r] / (right[r + 1] + left[j - r]);
                    Nv[r] = saved + right[r + 1] * temp;
                    saved = left[j - r] * temp;
                }
                Nv[j] = saved;
            }
            base = i - DEG;
            c0 = Nv[0]; c1 = Nv[1]; c2 = Nv[2]; c3 = Nv[3];
            sum = c0 * g_rowsum[base]     + c1 * g_rowsum[base + 1]
                + c2 * g_rowsum[base + 2] + c3 * g_rowsum[base + 3];
        }

        s_c[tl][0] = c0; s_c[tl][1] = c1; s_c[tl][2] = c2; s_c[tl][3] = c3;
        s_base[tl] = base;
        // b_splines_sum lives after the T*S b_splines block
        out[(size_t)T_TOTAL * S_DIM + tIdx] = sum;
    }
    __syncthreads();

    const int   base = s_base[tl];
    const float c0 = s_c[tl][0], c1 = s_c[tl][1], c2 = s_c[tl][2], c3 = s_c[tl][3];

    const int col = lane << 2;  // 4 columns per thread
    const float4 w0 = __ldg((const float4*)(weights + (base    ) * S_DIM + col));
    const float4 w1 = __ldg((const float4*)(weights + (base + 1) * S_DIM + col));
    const float4 w2 = __ldg((const float4*)(weights + (base + 2) * S_DIM + col));
    const float4 w3 = __ldg((const float4*)(weights + (base + 3) * S_DIM + col));

    float4 o;
    o.x = c0 * w0.x + c1 * w1.x + c2 * w2.x + c3 * w3.x;
    o.y = c0 * w0.y + c1 * w1.y + c2 * w2.y + c3 * w3.y;
    o.z = c0 * w0.z + c1 * w1.z + c2 * w2.z + c3 * w3.z;
    o.w = c0 * w0.w + c1 * w1.w + c2 * w2.w + c3 * w3.w;

    // Streaming store: 512 MB with zero reuse — don't pollute L2.
    __stcs((float4*)(out + (size_t)tIdx * S_DIM + col), o);
}

// ---------------------------------------------------------------------------
// Launch: inputs are (times, weights, knots) per metadata order.
// Output buffer: [ b_splines (T*S floats) | b_splines_sum (T floats) ].
// ---------------------------------------------------------------------------
extern "C" void kernel_launch(void* const* d_in, const int* in_sizes, int n_in,
                              void* d_out, int out_size) {
    const float* times   = (const float*)d_in[0];
    const float* weights = (const float*)d_in[1];
    const float* knots   = (const float*)d_in[2];
    float* out = (float*)d_out;

    rowsum_kernel<<<K_ROWS, 128>>>(weights);
    bspline_kernel<<<T_TOTAL / 4, 512>>>(times, weights, knots, out);
}

// round 7
// speedup vs baseline: 2.0607x; 2.0607x over previous
#include <cuda_runtime.h>

// Problem constants (fixed by the reference)
#define T_TOTAL   262144
#define S_DIM     512
#define K_ROWS    258       // NUM_KNOTS + DEGREE - 1
#define NKNOTS    262       // NUM_KNOTS + 2*DEGREE
#define DEG       3

#define TIMES_PER_BLOCK 64
#define NBLOCKS (T_TOTAL / TIMES_PER_BLOCK)   // 4096

// Scratch for weight row sums (allocation-free per harness rules)
__device__ float g_rowsum[K_ROWS];

// ---------------------------------------------------------------------------
// Kernel 1: rowsum[r] = sum_s W[r, s]   (258 x 512, negligible cost)
// ---------------------------------------------------------------------------
__global__ void rowsum_kernel(const float* __restrict__ weights) {
    const int row = blockIdx.x;
    float s = 0.0f;
    for (int c = threadIdx.x; c < S_DIM; c += blockDim.x)
        s += weights[row * S_DIM + c];
    #pragma unroll
    for (int o = 16; o > 0; o >>= 1)
        s += __shfl_down_sync(0xffffffffu, s, o);
    __shared__ float ws[4];
    const int w = threadIdx.x >> 5;
    if ((threadIdx.x & 31) == 0) ws[w] = s;
    __syncthreads();
    if (threadIdx.x == 0)
        g_rowsum[row] = ws[0] + ws[1] + ws[2] + ws[3];
}

// ---------------------------------------------------------------------------
// Kernel 2: 512 threads/block, 64 times/block.
//   Phase A: stage knots in smem.
//   Phase B: threads 0..63 each do an independent span search + de Boor for
//            one time (fully parallel — no serialized pointer chase), write
//            coeffs/base to smem and the per-time sum to gmem.
//   Phase C: 16 iterations x (4 times x 128 threads x float4) streaming
//            weight-combine + store.
// ---------------------------------------------------------------------------
__global__ __launch_bounds__(512)
void bspline_kernel(const float* __restrict__ times,
                    const float* __restrict__ weights,
                    const float* __restrict__ knots,
                    float* __restrict__ out)
{
    __shared__ float s_knots[NKNOTS];
    __shared__ float s_c[TIMES_PER_BLOCK][4];
    __shared__ int   s_base[TIMES_PER_BLOCK];

    const int tid = threadIdx.x;
    const int t0  = blockIdx.x * TIMES_PER_BLOCK;

    // Phase A: knots -> smem
    if (tid < NKNOTS) s_knots[tid] = knots[tid];
    __syncthreads();

    // Phase B: 64 parallel coefficient computations
    if (tid < TIMES_PER_BLOCK) {
        const float t = times[t0 + tid];
        float c0 = 0.f, c1 = 0.f, c2 = 0.f, c3 = 0.f, sum = 0.f;
        int base = 0;

        // Valid half-open span exists only if t < knots[258] (= t_max).
        // t == t_max => reference basis row is all zeros.
        if (t < s_knots[NKNOTS - DEG - 1]) {
            // binary search: largest i in [3, 257] with knots[i] <= t
            int lo = DEG, hi = NKNOTS - DEG - 2;   // 3 .. 257
            while (lo < hi) {
                const int mid = (lo + hi + 1) >> 1;
                if (s_knots[mid] <= t) lo = mid; else hi = mid - 1;
            }
            const int i = lo;  // knots[i] <= t < knots[i+1], non-empty span

            // Local de Boor triangle (all denominators > 0 in a valid span;
            // algebraically identical to the reference's recursion).
            float Nv[DEG + 1], left[DEG + 1], right[DEG + 1];
            Nv[0] = 1.0f;
            #pragma unroll
            for (int j = 1; j <= DEG; j++) {
                left[j]  = t - s_knots[i + 1 - j];
                right[j] = s_knots[i + j] - t;
                float saved = 0.0f;
                #pragma unroll
                for (int r = 0; r < j; r++) {
                    const float temp = Nv[r] / (right[r + 1] + left[j - r]);
                    Nv[r] = saved + right[r + 1] * temp;
                    saved = left[j - r] * temp;
                }
                Nv[j] = saved;
            }
            base = i - DEG;
            c0 = Nv[0]; c1 = Nv[1]; c2 = Nv[2]; c3 = Nv[3];
            sum = c0 * g_rowsum[base]     + c1 * g_rowsum[base + 1]
                + c2 * g_rowsum[base + 2] + c3 * g_rowsum[base + 3];
        }

        s_c[tid][0] = c0; s_c[tid][1] = c1; s_c[tid][2] = c2; s_c[tid][3] = c3;
        s_base[tid] = base;
        // b_splines_sum lives after the T*S b_splines block
        out[(size_t)T_TOTAL * S_DIM + (t0 + tid)] = sum;
    }
    __syncthreads();

    // Phase C: streaming combine + store
    const int tl   = tid >> 7;    // 0..3: time sub-slot
    const int lane = tid & 127;   // column group
    const int col  = lane << 2;   // 4 columns per thread

    #pragma unroll 4
    for (int it = 0; it < TIMES_PER_BLOCK / 4; ++it) {
        const int slot = (it << 2) + tl;          // 0..63
        const int base = s_base[slot];
        const float c0 = s_c[slot][0], c1 = s_c[slot][1];
        const float c2 = s_c[slot][2], c3 = s_c[slot][3];

        const float4 w0 = __ldg((const float4*)(weights + (base    ) * S_DIM + col));
        const float4 w1 = __ldg((const float4*)(weights + (base + 1) * S_DIM + col));
        const float4 w2 = __ldg((const float4*)(weights + (base + 2) * S_DIM + col));
        const float4 w3 = __ldg((const float4*)(weights + (base + 3) * S_DIM + col));

        float4 o;
        o.x = c0 * w0.x + c1 * w1.x + c2 * w2.x + c3 * w3.x;
        o.y = c0 * w0.y + c1 * w1.y + c2 * w2.y + c3 * w3.y;
        o.z = c0 * w0.z + c1 * w1.z + c2 * w2.z + c3 * w3.z;
        o.w = c0 * w0.w + c1 * w1.w + c2 * w2.w + c3 * w3.w;

        // Streaming store: 512 MB with zero reuse — don't pollute L2.
        __stcs((float4*)(out + (size_t)(t0 + slot) * S_DIM + col), o);
    }
}

// ---------------------------------------------------------------------------
// Launch: inputs are (times, weights, knots) per metadata order.
// Output buffer: [ b_splines (T*S floats) | b_splines_sum (T floats) ].
// ---------------------------------------------------------------------------
extern "C" void kernel_launch(void* const* d_in, const int* in_sizes, int n_in,
                              void* d_out, int out_size) {
    const float* times   = (const float*)d_in[0];
    const float* weights = (const float*)d_in[1];
    const float* knots   = (const float*)d_in[2];
    float* out = (float*)d_out;

    rowsum_kernel<<<K_ROWS, 128>>>(weights);
    bspline_kernel<<<NBLOCKS, 512>>>(times, weights, knots, out);
}

// round 8
// speedup vs baseline: 2.7363x; 1.3279x over previous
#include <cuda_runtime.h>

// Problem constants (fixed by the reference)
#define T_TOTAL   262144
#define S_DIM     512
#define K_ROWS    258       // NUM_KNOTS + DEGREE - 1
#define NKNOTS    262       // NUM_KNOTS + 2*DEGREE
#define DEG       3

#define TIMES_PER_BLOCK 64
#define NBLOCKS (T_TOTAL / TIMES_PER_BLOCK)   // 4096

// Scratch for weight row sums (allocation-free per harness rules)
__device__ float g_rowsum[K_ROWS];

// ---------------------------------------------------------------------------
// Kernel 1: rowsum[r] = sum_s W[r, s]   (258 x 512, negligible cost)
// ---------------------------------------------------------------------------
__global__ void rowsum_kernel(const float* __restrict__ weights) {
    const int row = blockIdx.x;
    float s = 0.0f;
    for (int c = threadIdx.x; c < S_DIM; c += blockDim.x)
        s += weights[row * S_DIM + c];
    #pragma unroll
    for (int o = 16; o > 0; o >>= 1)
        s += __shfl_down_sync(0xffffffffu, s, o);
    __shared__ float ws[4];
    const int w = threadIdx.x >> 5;
    if ((threadIdx.x & 31) == 0) ws[w] = s;
    __syncthreads();
    if (threadIdx.x == 0)
        g_rowsum[row] = ws[0] + ws[1] + ws[2] + ws[3];
}

// ---------------------------------------------------------------------------
// Kernel 2: 512 threads/block, 64 times/block.
//   Phase A: stage knots in smem.
//   Phase B: threads 0..63 do independent span search + de Boor, write
//            coeffs/base to smem + per-time sum to gmem.
//   Phase C: streaming combine + store. Weight rows are cached in registers
//            and reloaded only when the span base changes (warp-uniform
//            branch; base changes <= twice per block since times are sorted
//            and each knot span covers ~1028 times).
// ---------------------------------------------------------------------------
__global__ __launch_bounds__(512)
void bspline_kernel(const float* __restrict__ times,
                    const float* __restrict__ weights,
                    const float* __restrict__ knots,
                    float* __restrict__ out)
{
    __shared__ float s_knots[NKNOTS];
    __shared__ float s_c[TIMES_PER_BLOCK][4];
    __shared__ int   s_base[TIMES_PER_BLOCK];

    const int tid = threadIdx.x;
    const int t0  = blockIdx.x * TIMES_PER_BLOCK;

    // Phase A: knots -> smem
    if (tid < NKNOTS) s_knots[tid] = knots[tid];
    __syncthreads();

    // Phase B: 64 parallel coefficient computations
    if (tid < TIMES_PER_BLOCK) {
        const float t = times[t0 + tid];
        float c0 = 0.f, c1 = 0.f, c2 = 0.f, c3 = 0.f, sum = 0.f;
        int base = 0;

        // Valid half-open span exists only if t < knots[258] (= t_max).
        // t == t_max => reference basis row is all zeros.
        if (t < s_knots[NKNOTS - DEG - 1]) {
            // binary search: largest i in [3, 257] with knots[i] <= t
            int lo = DEG, hi = NKNOTS - DEG - 2;   // 3 .. 257
            while (lo < hi) {
                const int mid = (lo + hi + 1) >> 1;
                if (s_knots[mid] <= t) lo = mid; else hi = mid - 1;
            }
            const int i = lo;  // knots[i] <= t < knots[i+1], non-empty span

            // Local de Boor triangle (all denominators > 0 in a valid span;
            // algebraically identical to the reference's recursion).
            float Nv[DEG + 1], left[DEG + 1], right[DEG + 1];
            Nv[0] = 1.0f;
            #pragma unroll
            for (int j = 1; j <= DEG; j++) {
                left[j]  = t - s_knots[i + 1 - j];
                right[j] = s_knots[i + j] - t;
                float saved = 0.0f;
                #pragma unroll
                for (int r = 0; r < j; r++) {
                    const float temp = Nv[r] / (right[r + 1] + left[j - r]);
                    Nv[r] = saved + right[r + 1] * temp;
                    saved = left[j - r] * temp;
                }
                Nv[j] = saved;
            }
            base = i - DEG;
            c0 = Nv[0]; c1 = Nv[1]; c2 = Nv[2]; c3 = Nv[3];
            sum = c0 * g_rowsum[base]     + c1 * g_rowsum[base + 1]
                + c2 * g_rowsum[base + 2] + c3 * g_rowsum[base + 3];
        }

        s_c[tid][0] = c0; s_c[tid][1] = c1; s_c[tid][2] = c2; s_c[tid][3] = c3;
        s_base[tid] = base;
        // b_splines_sum lives after the T*S b_splines block
        out[(size_t)T_TOTAL * S_DIM + (t0 + tid)] = sum;
    }
    __syncthreads();

    // Phase C: streaming combine + store with register-cached weight rows
    const int tl   = tid >> 7;    // 0..3: time sub-slot (warp-uniform)
    const int lane = tid & 127;   // column group
    const int col  = lane << 2;   // 4 columns per thread

    // Prime the weight-row register cache with the first slot's base
    int curBase = s_base[tl];
    const float* wp = weights + (size_t)curBase * S_DIM + col;
    float4 w0 = __ldg((const float4*)(wp));
    float4 w1 = __ldg((const float4*)(wp + S_DIM));
    float4 w2 = __ldg((const float4*)(wp + 2 * S_DIM));
    float4 w3 = __ldg((const float4*)(wp + 3 * S_DIM));

    #pragma unroll 4
    for (int it = 0; it < TIMES_PER_BLOCK / 4; ++it) {
        const int slot = (it << 2) + tl;          // 0..63 (warp-uniform)
        const int base = s_base[slot];
        if (base != curBase) {                     // warp-uniform, rare
            curBase = base;
            const float* wq = weights + (size_t)base * S_DIM + col;
            w0 = __ldg((const float4*)(wq));
            w1 = __ldg((const float4*)(wq + S_DIM));
            w2 = __ldg((const float4*)(wq + 2 * S_DIM));
            w3 = __ldg((const float4*)(wq + 3 * S_DIM));
        }
        const float c0 = s_c[slot][0], c1 = s_c[slot][1];
        const float c2 = s_c[slot][2], c3 = s_c[slot][3];

        float4 o;
        o.x = c0 * w0.x + c1 * w1.x + c2 * w2.x + c3 * w3.x;
        o.y = c0 * w0.y + c1 * w1.y + c2 * w2.y + c3 * w3.y;
        o.z = c0 * w0.z + c1 * w1.z + c2 * w2.z + c3 * w3.z;
        o.w = c0 * w0.w + c1 * w1.w + c2 * w2.w + c3 * w3.w;

        // Streaming store: 512 MB with zero reuse — don't pollute L2.
        __stcs((float4*)(out + (size_t)(t0 + slot) * S_DIM + col), o);
    }
}

// ---------------------------------------------------------------------------
// Launch: inputs are (times, weights, knots) per metadata order.
// Output buffer: [ b_splines (T*S floats) | b_splines_sum (T floats) ].
// ---------------------------------------------------------------------------
extern "C" void kernel_launch(void* const* d_in, const int* in_sizes, int n_in,
                              void* d_out, int out_size) {
    const float* times   = (const float*)d_in[0];
    const float* weights = (const float*)d_in[1];
    const float* knots   = (const float*)d_in[2];
    float* out = (float*)d_out;

    rowsum_kernel<<<K_ROWS, 128>>>(weights);
    bspline_kernel<<<NBLOCKS, 512>>>(times, weights, knots, out);
}